// round 1
// baseline (speedup 1.0000x reference)
#include <cuda_runtime.h>
#include <cuda_bf16.h>

// Scratch (allocation-free contract: __device__ globals)
#define N_NODES_MAX 100000
#define F 128
__device__ float g_agg[(long)N_NODES_MAX * F];   // 51.2 MB
__device__ float g_deg[N_NODES_MAX];             // 0.4 MB

// ---------------------------------------------------------------------------
// Kernel 1: zero the aggregation buffer and degree counts
// ---------------------------------------------------------------------------
__global__ void zero_kernel(int n_nodes) {
    long total4 = (long)n_nodes * F / 4;     // float4 count for agg
    float4 z = make_float4(0.f, 0.f, 0.f, 0.f);
    for (long i = (long)blockIdx.x * blockDim.x + threadIdx.x;
         i < total4; i += (long)gridDim.x * blockDim.x) {
        reinterpret_cast<float4*>(g_agg)[i] = z;
    }
    for (int i = blockIdx.x * blockDim.x + threadIdx.x;
         i < n_nodes; i += gridDim.x * blockDim.x) {
        g_deg[i] = 0.f;
    }
}

// ---------------------------------------------------------------------------
// Kernel 2: edge scatter-add. One warp per edge; each lane owns 4 features.
//   agg[dst] += feat[src];  deg[dst] += 1
// atomicAdd with unused return compiles to REDG (no round trip).
// ---------------------------------------------------------------------------
__global__ void scatter_kernel(const float* __restrict__ feat,
                               const int* __restrict__ src,
                               const int* __restrict__ dst,
                               int n_edges) {
    long t = (long)blockIdx.x * blockDim.x + threadIdx.x;
    long e = t >> 5;
    if (e >= n_edges) return;
    int lane = (int)(t & 31);

    int s = __ldg(src + e);
    int d = __ldg(dst + e);

    const float4 v = *reinterpret_cast<const float4*>(feat + (long)s * F + lane * 4);
    float* a = g_agg + (long)d * F + lane * 4;
    atomicAdd(a + 0, v.x);
    atomicAdd(a + 1, v.y);
    atomicAdd(a + 2, v.z);
    atomicAdd(a + 3, v.w);
    if (lane == 0) atomicAdd(&g_deg[d], 1.0f);
}

// ---------------------------------------------------------------------------
// Kernel 3: out = (agg @ W) * rsqrt(max(deg,1)) + bias
// Block = 128 threads, handles 32 rows. agg tile staged in smem (16 KB),
// W streamed column-coalesced (L2-resident after first wave).
// Thread j owns output column j for all 32 rows (32 fp32 accumulators).
// ---------------------------------------------------------------------------
#define ROWS_PER_BLOCK 32
__global__ void __launch_bounds__(128) gemm_norm_kernel(
        const float* __restrict__ W,
        const float* __restrict__ bias,
        float* __restrict__ out,
        int n_nodes) {
    __shared__ float sA[ROWS_PER_BLOCK * F];

    int rb = blockIdx.x * ROWS_PER_BLOCK;
    int j = threadIdx.x;  // output column, 0..127

    // Cooperative load of 32 contiguous rows (fully coalesced float4)
    const float4* ap = reinterpret_cast<const float4*>(g_agg + (long)rb * F);
    float4* sp = reinterpret_cast<float4*>(sA);
#pragma unroll
    for (int i = 0; i < (ROWS_PER_BLOCK * F / 4) / 128; i++) {
        sp[j + i * 128] = ap[j + i * 128];
    }
    __syncthreads();

    float acc[ROWS_PER_BLOCK];
#pragma unroll
    for (int r = 0; r < ROWS_PER_BLOCK; r++) acc[r] = 0.f;

    for (int k = 0; k < F; k++) {
        float w = __ldg(W + k * F + j);   // coalesced across j, broadcast over rows
#pragma unroll
        for (int r = 0; r < ROWS_PER_BLOCK; r++) {
            acc[r] = fmaf(sA[r * F + k], w, acc[r]);
        }
    }

    float b = __ldg(bias + j);
#pragma unroll
    for (int r = 0; r < ROWS_PER_BLOCK; r++) {
        int row = rb + r;
        if (row < n_nodes) {
            float nrm = rsqrtf(fmaxf(g_deg[row], 1.0f));
            out[(long)row * F + j] = acc[r] * nrm + b;
        }
    }
}

// ---------------------------------------------------------------------------
// Launch. Inputs (metadata order): feat f32[100000*128], src i32[1.6M],
// dst i32[1.6M], weight f32[128*128], bias f32[128]. Output f32[100000*128].
// ---------------------------------------------------------------------------
extern "C" void kernel_launch(void* const* d_in, const int* in_sizes, int n_in,
                              void* d_out, int out_size) {
    const float* feat   = (const float*)d_in[0];
    const int*   src    = (const int*)d_in[1];
    const int*   dst    = (const int*)d_in[2];
    const float* weight = (const float*)d_in[3];
    const float* bias   = (const float*)d_in[4];
    float* out = (float*)d_out;

    int n_nodes = in_sizes[0] / F;
    int n_edges = in_sizes[1];

    zero_kernel<<<2048, 256>>>(n_nodes);

    long scatter_threads = (long)n_edges * 32;
    int scatter_blocks = (int)((scatter_threads + 255) / 256);
    scatter_kernel<<<scatter_blocks, 256>>>(feat, src, dst, n_edges);

    int gemm_blocks = (n_nodes + ROWS_PER_BLOCK - 1) / ROWS_PER_BLOCK;
    gemm_norm_kernel<<<gemm_blocks, 128>>>(weight, bias, out, n_nodes);
}

// round 2
// speedup vs baseline: 1.5792x; 1.5792x over previous
#include <cuda_runtime.h>
#include <cuda_bf16.h>

// Scratch (allocation-free contract: __device__ globals)
#define N_NODES_MAX 100000
#define F 128
__device__ float g_agg[(long)N_NODES_MAX * F];   // 51.2 MB
__device__ float g_deg[N_NODES_MAX];             // 0.4 MB

// ---------------------------------------------------------------------------
// Kernel 1: zero the aggregation buffer and degree counts
// ---------------------------------------------------------------------------
__global__ void zero_kernel(int n_nodes) {
    long total4 = (long)n_nodes * F / 4;     // float4 count for agg
    float4 z = make_float4(0.f, 0.f, 0.f, 0.f);
    for (long i = (long)blockIdx.x * blockDim.x + threadIdx.x;
         i < total4; i += (long)gridDim.x * blockDim.x) {
        reinterpret_cast<float4*>(g_agg)[i] = z;
    }
    for (int i = blockIdx.x * blockDim.x + threadIdx.x;
         i < n_nodes; i += gridDim.x * blockDim.x) {
        g_deg[i] = 0.f;
    }
}

// ---------------------------------------------------------------------------
// Kernel 2: edge scatter-add. One warp per edge; each lane owns 4 features.
//   agg[dst] += feat[src];  deg[dst] += 1
// red.global.add.v4.f32: one vectorized no-return reduction per lane
// (16B/instr) instead of 4 scalar REDs — 4x fewer RED issues.
// ---------------------------------------------------------------------------
__global__ void scatter_kernel(const float* __restrict__ feat,
                               const int* __restrict__ src,
                               const int* __restrict__ dst,
                               int n_edges) {
    long t = (long)blockIdx.x * blockDim.x + threadIdx.x;
    long e = t >> 5;
    if (e >= n_edges) return;
    int lane = (int)(t & 31);

    int s = __ldg(src + e);
    int d = __ldg(dst + e);

    const float4 v = *reinterpret_cast<const float4*>(feat + (long)s * F + lane * 4);
    float* a = g_agg + (long)d * F + lane * 4;
    asm volatile("red.global.add.v4.f32 [%0], {%1, %2, %3, %4};"
                 :: "l"(a), "f"(v.x), "f"(v.y), "f"(v.z), "f"(v.w)
                 : "memory");
    if (lane == 0) atomicAdd(&g_deg[d], 1.0f);
}

// ---------------------------------------------------------------------------
// Kernel 3: out = (agg @ W) * rsqrt(max(deg,1)) + bias
// Block = 128 threads, handles 32 rows. agg tile staged in smem (16 KB),
// W streamed column-coalesced (L2-resident after first wave).
// Thread j owns output column j for all 32 rows (32 fp32 accumulators).
// ---------------------------------------------------------------------------
#define ROWS_PER_BLOCK 32
__global__ void __launch_bounds__(128) gemm_norm_kernel(
        const float* __restrict__ W,
        const float* __restrict__ bias,
        float* __restrict__ out,
        int n_nodes) {
    __shared__ float sA[ROWS_PER_BLOCK * F];

    int rb = blockIdx.x * ROWS_PER_BLOCK;
    int j = threadIdx.x;  // output column, 0..127

    // Cooperative load of 32 contiguous rows (fully coalesced float4)
    const float4* ap = reinterpret_cast<const float4*>(g_agg + (long)rb * F);
    float4* sp = reinterpret_cast<float4*>(sA);
#pragma unroll
    for (int i = 0; i < (ROWS_PER_BLOCK * F / 4) / 128; i++) {
        sp[j + i * 128] = ap[j + i * 128];
    }
    __syncthreads();

    float acc[ROWS_PER_BLOCK];
#pragma unroll
    for (int r = 0; r < ROWS_PER_BLOCK; r++) acc[r] = 0.f;

    for (int k = 0; k < F; k++) {
        float w = __ldg(W + k * F + j);   // coalesced across j, broadcast over rows
#pragma unroll
        for (int r = 0; r < ROWS_PER_BLOCK; r++) {
            acc[r] = fmaf(sA[r * F + k], w, acc[r]);
        }
    }

    float b = __ldg(bias + j);
#pragma unroll
    for (int r = 0; r < ROWS_PER_BLOCK; r++) {
        int row = rb + r;
        if (row < n_nodes) {
            float nrm = rsqrtf(fmaxf(g_deg[row], 1.0f));
            out[(long)row * F + j] = acc[r] * nrm + b;
        }
    }
}

// ---------------------------------------------------------------------------
// Launch. Inputs (metadata order): feat f32[100000*128], src i32[1.6M],
// dst i32[1.6M], weight f32[128*128], bias f32[128]. Output f32[100000*128].
// ---------------------------------------------------------------------------
extern "C" void kernel_launch(void* const* d_in, const int* in_sizes, int n_in,
                              void* d_out, int out_size) {
    const float* feat   = (const float*)d_in[0];
    const int*   src    = (const int*)d_in[1];
    const int*   dst    = (const int*)d_in[2];
    const float* weight = (const float*)d_in[3];
    const float* bias   = (const float*)d_in[4];
    float* out = (float*)d_out;

    int n_nodes = in_sizes[0] / F;
    int n_edges = in_sizes[1];

    zero_kernel<<<2048, 256>>>(n_nodes);

    long scatter_threads = (long)n_edges * 32;
    int scatter_blocks = (int)((scatter_threads + 255) / 256);
    scatter_kernel<<<scatter_blocks, 256>>>(feat, src, dst, n_edges);

    int gemm_blocks = (n_nodes + ROWS_PER_BLOCK - 1) / ROWS_PER_BLOCK;
    gemm_norm_kernel<<<gemm_blocks, 128>>>(weight, bias, out, n_nodes);
}

// round 3
// speedup vs baseline: 2.0972x; 1.3280x over previous
#include <cuda_runtime.h>
#include <cuda_bf16.h>

#define N_NODES_MAX 100000
#define E_MAX       1600000
#define F           128
#define SCAN_CHUNK  1024
#define SCAN_GMAX   128      // ceil(100000/1024) = 98 <= 128

// Scratch (allocation-free contract: __device__ globals)
__device__ float g_agg[(long)N_NODES_MAX * F];     // 51.2 MB
__device__ int   g_deg[N_NODES_MAX];
__device__ int   g_row_start[N_NODES_MAX + 1];
__device__ int   g_cursor[N_NODES_MAX];
__device__ int   g_csr_src[E_MAX];                 // 6.4 MB
__device__ int   g_block_sums[SCAN_GMAX];
__device__ int   g_block_offsets[SCAN_GMAX];

// ---------------------------------------------------------------------------
// 1. zero degree counts + cursors
// ---------------------------------------------------------------------------
__global__ void zero_counts_kernel(int n_nodes) {
    int i = blockIdx.x * blockDim.x + threadIdx.x;
    if (i < n_nodes) { g_deg[i] = 0; g_cursor[i] = 0; }
}

// ---------------------------------------------------------------------------
// 2. histogram of dst (int REDs, spread addresses — fast path)
// ---------------------------------------------------------------------------
__global__ void hist_kernel(const int* __restrict__ dst, int n_edges) {
    int e = blockIdx.x * blockDim.x + threadIdx.x;
    if (e < n_edges) atomicAdd(&g_deg[dst[e]], 1);
}

// ---------------------------------------------------------------------------
// 3a. per-chunk sums
// ---------------------------------------------------------------------------
__global__ void __launch_bounds__(SCAN_CHUNK) scan1_kernel(int n_nodes) {
    __shared__ int s[SCAN_CHUNK];
    int t = threadIdx.x;
    int idx = blockIdx.x * SCAN_CHUNK + t;
    s[t] = (idx < n_nodes) ? g_deg[idx] : 0;
    __syncthreads();
    for (int off = SCAN_CHUNK / 2; off > 0; off >>= 1) {
        if (t < off) s[t] += s[t + off];
        __syncthreads();
    }
    if (t == 0) g_block_sums[blockIdx.x] = s[0];
}

// 3b. scan of chunk sums (single block), also writes row_start[n_nodes]
__global__ void __launch_bounds__(SCAN_GMAX) scan2_kernel(int n_blocks, int n_nodes) {
    __shared__ int s[SCAN_GMAX];
    int t = threadIdx.x;
    int v = (t < n_blocks) ? g_block_sums[t] : 0;
    s[t] = v;
    __syncthreads();
    for (int off = 1; off < SCAN_GMAX; off <<= 1) {
        int add = (t >= off) ? s[t - off] : 0;
        __syncthreads();
        s[t] += add;
        __syncthreads();
    }
    if (t < n_blocks) g_block_offsets[t] = s[t] - v;   // exclusive
    if (t == SCAN_GMAX - 1) g_row_start[n_nodes] = s[SCAN_GMAX - 1];
}

// 3c. per-chunk exclusive scan + block offset -> row_start
__global__ void __launch_bounds__(SCAN_CHUNK) scan3_kernel(int n_nodes) {
    __shared__ int s[SCAN_CHUNK];
    int t = threadIdx.x;
    int idx = blockIdx.x * SCAN_CHUNK + t;
    int own = (idx < n_nodes) ? g_deg[idx] : 0;
    s[t] = own;
    __syncthreads();
    for (int off = 1; off < SCAN_CHUNK; off <<= 1) {
        int add = (t >= off) ? s[t - off] : 0;
        __syncthreads();
        s[t] += add;
        __syncthreads();
    }
    if (idx < n_nodes)
        g_row_start[idx] = g_block_offsets[blockIdx.x] + s[t] - own;
}

// ---------------------------------------------------------------------------
// 4. fill CSR: slot = row_start[dst] + cursor[dst]++
// ---------------------------------------------------------------------------
__global__ void fill_kernel(const int* __restrict__ src,
                            const int* __restrict__ dst, int n_edges) {
    int e = blockIdx.x * blockDim.x + threadIdx.x;
    if (e >= n_edges) return;
    int d = dst[e];
    int pos = atomicAdd(&g_cursor[d], 1);
    g_csr_src[g_row_start[d] + pos] = src[e];
}

// ---------------------------------------------------------------------------
// 5. gather: one warp per node. Lanes own 4 features; edge src indices are
// loaded 32-at-a-time and shfl-broadcast. Plain LDG.128 reads, one float4
// store per lane — zero float atomics.
// ---------------------------------------------------------------------------
__global__ void __launch_bounds__(256) gather_kernel(
        const float* __restrict__ feat, int n_nodes) {
    int node = blockIdx.x * (blockDim.x >> 5) + (threadIdx.x >> 5);
    if (node >= n_nodes) return;
    int lane = threadIdx.x & 31;

    int beg = g_row_start[node];
    int end = g_row_start[node + 1];

    float4 acc = make_float4(0.f, 0.f, 0.f, 0.f);
    for (int i = beg; i < end; i += 32) {
        int s_reg = (i + lane < end) ? g_csr_src[i + lane] : 0;
        int cnt = min(32, end - i);
#pragma unroll 4
        for (int j = 0; j < cnt; j++) {
            int s = __shfl_sync(0xffffffffu, s_reg, j);
            const float4 v = *reinterpret_cast<const float4*>(
                feat + (long)s * F + lane * 4);
            acc.x += v.x; acc.y += v.y; acc.z += v.z; acc.w += v.w;
        }
    }
    *reinterpret_cast<float4*>(g_agg + (long)node * F + lane * 4) = acc;
}

// ---------------------------------------------------------------------------
// 6. out = (agg @ W) * rsqrt(max(deg,1)) + bias
// ---------------------------------------------------------------------------
#define ROWS_PER_BLOCK 32
__global__ void __launch_bounds__(128) gemm_norm_kernel(
        const float* __restrict__ W,
        const float* __restrict__ bias,
        float* __restrict__ out,
        int n_nodes) {
    __shared__ float sA[ROWS_PER_BLOCK * F];

    int rb = blockIdx.x * ROWS_PER_BLOCK;
    int j = threadIdx.x;  // output column

    const float4* ap = reinterpret_cast<const float4*>(g_agg + (long)rb * F);
    float4* sp = reinterpret_cast<float4*>(sA);
#pragma unroll
    for (int i = 0; i < (ROWS_PER_BLOCK * F / 4) / 128; i++)
        sp[j + i * 128] = ap[j + i * 128];
    __syncthreads();

    float acc[ROWS_PER_BLOCK];
#pragma unroll
    for (int r = 0; r < ROWS_PER_BLOCK; r++) acc[r] = 0.f;

    for (int k = 0; k < F; k++) {
        float w = __ldg(W + k * F + j);
#pragma unroll
        for (int r = 0; r < ROWS_PER_BLOCK; r++)
            acc[r] = fmaf(sA[r * F + k], w, acc[r]);
    }

    float b = __ldg(bias + j);
#pragma unroll
    for (int r = 0; r < ROWS_PER_BLOCK; r++) {
        int row = rb + r;
        if (row < n_nodes) {
            float nrm = rsqrtf(fmaxf((float)g_deg[row], 1.0f));
            out[(long)row * F + j] = acc[r] * nrm + b;
        }
    }
}

// ---------------------------------------------------------------------------
extern "C" void kernel_launch(void* const* d_in, const int* in_sizes, int n_in,
                              void* d_out, int out_size) {
    const float* feat   = (const float*)d_in[0];
    const int*   src    = (const int*)d_in[1];
    const int*   dst    = (const int*)d_in[2];
    const float* weight = (const float*)d_in[3];
    const float* bias   = (const float*)d_in[4];
    float* out = (float*)d_out;

    int n_nodes = in_sizes[0] / F;
    int n_edges = in_sizes[1];

    int scan_blocks = (n_nodes + SCAN_CHUNK - 1) / SCAN_CHUNK;
    int eb = (n_edges + 255) / 256;

    zero_counts_kernel<<<(n_nodes + 255) / 256, 256>>>(n_nodes);
    hist_kernel<<<eb, 256>>>(dst, n_edges);
    scan1_kernel<<<scan_blocks, SCAN_CHUNK>>>(n_nodes);
    scan2_kernel<<<1, SCAN_GMAX>>>(scan_blocks, n_nodes);
    scan3_kernel<<<scan_blocks, SCAN_CHUNK>>>(n_nodes);
    fill_kernel<<<eb, 256>>>(src, dst, n_edges);

    int warps_per_block = 256 / 32;
    int gather_blocks = (n_nodes + warps_per_block - 1) / warps_per_block;
    gather_kernel<<<gather_blocks, 256>>>(feat, n_nodes);

    int gemm_blocks = (n_nodes + ROWS_PER_BLOCK - 1) / ROWS_PER_BLOCK;
    gemm_norm_kernel<<<gemm_blocks, 128>>>(weight, bias, out, n_nodes);
}

// round 5
// speedup vs baseline: 3.1209x; 1.4882x over previous
#include <cuda_runtime.h>
#include <cuda_bf16.h>

#define N_NODES_MAX 100000
#define E_MAX       1600000
#define F           128
#define SCAN_CHUNK  1024
#define SCAN_GMAX   128      // ceil(100000/1024) = 98 <= 128

// Scratch (allocation-free contract: __device__ globals)
__device__ float g_agg[(long)N_NODES_MAX * F];     // 51.2 MB
__device__ int   g_deg[N_NODES_MAX];
__device__ int   g_row_start[N_NODES_MAX + 1];
__device__ int   g_cursor[N_NODES_MAX];
__device__ int   g_csr_src[E_MAX];                 // 6.4 MB
__device__ int   g_block_sums[SCAN_GMAX];
__device__ int   g_block_offsets[SCAN_GMAX];

// ---------------------------------------------------------------------------
// 1. zero degree counts + cursors
// ---------------------------------------------------------------------------
__global__ void zero_counts_kernel(int n_nodes) {
    int i = blockIdx.x * blockDim.x + threadIdx.x;
    if (i < n_nodes) { g_deg[i] = 0; g_cursor[i] = 0; }
}

// ---------------------------------------------------------------------------
// 2. histogram of dst
// ---------------------------------------------------------------------------
__global__ void hist_kernel(const int* __restrict__ dst, int n_edges) {
    int e = blockIdx.x * blockDim.x + threadIdx.x;
    if (e < n_edges) atomicAdd(&g_deg[dst[e]], 1);
}

// ---------------------------------------------------------------------------
// 3a. per-chunk sums
// ---------------------------------------------------------------------------
__global__ void __launch_bounds__(SCAN_CHUNK) scan1_kernel(int n_nodes) {
    __shared__ int s[SCAN_CHUNK];
    int t = threadIdx.x;
    int idx = blockIdx.x * SCAN_CHUNK + t;
    s[t] = (idx < n_nodes) ? g_deg[idx] : 0;
    __syncthreads();
    for (int off = SCAN_CHUNK / 2; off > 0; off >>= 1) {
        if (t < off) s[t] += s[t + off];
        __syncthreads();
    }
    if (t == 0) g_block_sums[blockIdx.x] = s[0];
}

// 3b. scan of chunk sums (single block)
__global__ void __launch_bounds__(SCAN_GMAX) scan2_kernel(int n_blocks, int n_nodes) {
    __shared__ int s[SCAN_GMAX];
    int t = threadIdx.x;
    int v = (t < n_blocks) ? g_block_sums[t] : 0;
    s[t] = v;
    __syncthreads();
    for (int off = 1; off < SCAN_GMAX; off <<= 1) {
        int add = (t >= off) ? s[t - off] : 0;
        __syncthreads();
        s[t] += add;
        __syncthreads();
    }
    if (t < n_blocks) g_block_offsets[t] = s[t] - v;   // exclusive
    if (t == SCAN_GMAX - 1) g_row_start[n_nodes] = s[SCAN_GMAX - 1];
}

// 3c. per-chunk exclusive scan + block offset -> row_start
__global__ void __launch_bounds__(SCAN_CHUNK) scan3_kernel(int n_nodes) {
    __shared__ int s[SCAN_CHUNK];
    int t = threadIdx.x;
    int idx = blockIdx.x * SCAN_CHUNK + t;
    int own = (idx < n_nodes) ? g_deg[idx] : 0;
    s[t] = own;
    __syncthreads();
    for (int off = 1; off < SCAN_CHUNK; off <<= 1) {
        int add = (t >= off) ? s[t - off] : 0;
        __syncthreads();
        s[t] += add;
        __syncthreads();
    }
    if (idx < n_nodes)
        g_row_start[idx] = g_block_offsets[blockIdx.x] + s[t] - own;
}

// ---------------------------------------------------------------------------
// 4. fill CSR: slot = row_start[dst] + cursor[dst]++
// ---------------------------------------------------------------------------
__global__ void fill_kernel(const int* __restrict__ src,
                            const int* __restrict__ dst, int n_edges) {
    int e = blockIdx.x * blockDim.x + threadIdx.x;
    if (e >= n_edges) return;
    int d = dst[e];
    int pos = atomicAdd(&g_cursor[d], 1);
    g_csr_src[g_row_start[d] + pos] = src[e];
}

// ---------------------------------------------------------------------------
// 5. gather: one warp per node. Lanes own 4 features; edge src indices
// shfl-broadcast; unroll 8 for MLP on L2-hit loads.
// ---------------------------------------------------------------------------
__global__ void __launch_bounds__(256) gather_kernel(
        const float* __restrict__ feat, int n_nodes) {
    int node = blockIdx.x * (blockDim.x >> 5) + (threadIdx.x >> 5);
    if (node >= n_nodes) return;
    int lane = threadIdx.x & 31;

    int beg = g_row_start[node];
    int end = g_row_start[node + 1];

    float4 acc = make_float4(0.f, 0.f, 0.f, 0.f);
    for (int i = beg; i < end; i += 32) {
        int s_reg = (i + lane < end) ? g_csr_src[i + lane] : 0;
        int cnt = min(32, end - i);
#pragma unroll 8
        for (int j = 0; j < cnt; j++) {
            int s = __shfl_sync(0xffffffffu, s_reg, j);
            const float4 v = *reinterpret_cast<const float4*>(
                feat + (long)s * F + lane * 4);
            acc.x += v.x; acc.y += v.y; acc.z += v.z; acc.w += v.w;
        }
    }
    *reinterpret_cast<float4*>(g_agg + (long)node * F + lane * 4) = acc;
}

// ---------------------------------------------------------------------------
// 6. register-tiled GEMM + norm + bias.
// Block: 256 threads, tile 64 rows x 128 cols. Thread micro-tile: 8 rows x
// 4 cols. Per k: 8 broadcast LDS.32 (a, same addr warp-wide) + 1 LDG.128
// (w float4, L1-resident) + 32 FFMA -> 41 instr / 32 FMA.
// ---------------------------------------------------------------------------
#define GM 64
__global__ void __launch_bounds__(256) gemm_norm_kernel(
        const float* __restrict__ W,
        const float* __restrict__ bias,
        float* __restrict__ out,
        int n_nodes) {
    __shared__ float sA[GM * F];   // 32 KB

    int t = threadIdx.x;
    int rb = blockIdx.x * GM;

    // Cooperative load of 64 rows (coalesced float4), zero-pad OOB rows.
    {
        const float4* ap = reinterpret_cast<const float4*>(g_agg);
        float4* sp = reinterpret_cast<float4*>(sA);
#pragma unroll
        for (int i = 0; i < (GM * F / 4) / 256; i++) {
            int idx = t + i * 256;            // float4 index in tile
            int row = rb + (idx >> 5);        // 32 float4 per row
            sp[idx] = (row < n_nodes) ? ap[(long)rb * 32 + idx]
                                      : make_float4(0.f, 0.f, 0.f, 0.f);
        }
    }
    __syncthreads();

    int cg = (t & 31) * 4;   // col base (0..124)
    int rg = (t >> 5) * 8;   // row base within tile (0..56)

    float acc[8][4];
#pragma unroll
    for (int i = 0; i < 8; i++)
#pragma unroll
        for (int j = 0; j < 4; j++) acc[i][j] = 0.f;

#pragma unroll 8
    for (int k = 0; k < F; k++) {
        float4 w = __ldg(reinterpret_cast<const float4*>(W + k * F + cg));
#pragma unroll
        for (int i = 0; i < 8; i++) {
            float a = sA[(rg + i) * F + k];   // broadcast across warp
            acc[i][0] = fmaf(a, w.x, acc[i][0]);
            acc[i][1] = fmaf(a, w.y, acc[i][1]);
            acc[i][2] = fmaf(a, w.z, acc[i][2]);
            acc[i][3] = fmaf(a, w.w, acc[i][3]);
        }
    }

    float4 b = __ldg(reinterpret_cast<const float4*>(bias + cg));
#pragma unroll
    for (int i = 0; i < 8; i++) {
        int row = rb + rg + i;
        if (row < n_nodes) {
            float nrm = rsqrtf(fmaxf((float)g_deg[row], 1.0f));
            float4 o;
            o.x = acc[i][0] * nrm + b.x;
            o.y = acc[i][1] * nrm + b.y;
            o.z = acc[i][2] * nrm + b.z;
            o.w = acc[i][3] * nrm + b.w;
            *reinterpret_cast<float4*>(out + (long)row * F + cg) = o;
        }
    }
}

// ---------------------------------------------------------------------------
extern "C" void kernel_launch(void* const* d_in, const int* in_sizes, int n_in,
                              void* d_out, int out_size) {
    const float* feat   = (const float*)d_in[0];
    const int*   src    = (const int*)d_in[1];
    const int*   dst    = (const int*)d_in[2];
    const float* weight = (const float*)d_in[3];
    const float* bias   = (const float*)d_in[4];
    float* out = (float*)d_out;

    int n_nodes = in_sizes[0] / F;
    int n_edges = in_sizes[1];

    int scan_blocks = (n_nodes + SCAN_CHUNK - 1) / SCAN_CHUNK;
    int eb = (n_edges + 255) / 256;

    zero_counts_kernel<<<(n_nodes + 255) / 256, 256>>>(n_nodes);
    hist_kernel<<<eb, 256>>>(dst, n_edges);
    scan1_kernel<<<scan_blocks, SCAN_CHUNK>>>(n_nodes);
    scan2_kernel<<<1, SCAN_GMAX>>>(scan_blocks, n_nodes);
    scan3_kernel<<<scan_blocks, SCAN_CHUNK>>>(n_nodes);
    fill_kernel<<<eb, 256>>>(src, dst, n_edges);

    int warps_per_block = 256 / 32;
    int gather_blocks = (n_nodes + warps_per_block - 1) / warps_per_block;
    gather_kernel<<<gather_blocks, 256>>>(feat, n_nodes);

    int gemm_blocks = (n_nodes + GM - 1) / GM;
    gemm_norm_kernel<<<gemm_blocks, 256>>>(weight, bias, out, n_nodes);
}